// round 1
// baseline (speedup 1.0000x reference)
#include <cuda_runtime.h>
#include <math.h>

// ---------------- problem constants ----------------
constexpr int N_  = 50000;
constexpr int E_  = 600000;
constexpr int H_  = 128;
constexpr int G_  = 50;
constexpr int NF_ = 128;
constexpr int L_  = 6;
constexpr int NC_ = 500;
constexpr int NM_ = 100;

constexpr float CUTOFF = 10.0f;
constexpr float GSTEP  = CUTOFF / (G_ - 1);            // 10/49
constexpr float COEFF  = -0.5f / (GSTEP * GSTEP);
constexpr float LOG2F_ = 0.6931471805599453f;
constexpr float PI_    = 3.14159265358979323846f;

// ---------------- scratch (device globals; no allocation allowed) ----------------
__device__ float g_h   [N_ * H_];
__device__ float g_xf  [N_ * NF_];
__device__ float g_agg [N_ * NF_];
__device__ float g_tmp [N_ * H_];
__device__ float g_h2  [N_ * H_];
__device__ float g_dE  [E_];
__device__ float g_CE  [E_];
__device__ float g_conf[NC_ * H_];
__device__ float g_mol [NM_ * H_];

// ---------------- helpers ----------------
__device__ __forceinline__ float sspf(float x) {
    // shifted softplus: log1p(exp(x)) - log(2), numerically stable
    float ex = __expf(-fabsf(x));
    return fmaxf(x, 0.0f) + __logf(1.0f + ex) - LOG2F_;
}

// ---------------- embed: h = emb_table[z] ----------------
__global__ void embed_kernel(const int* __restrict__ z, const float* __restrict__ emb,
                             float* __restrict__ h) {
    int idx = blockIdx.x * blockDim.x + threadIdx.x;
    if (idx < N_ * H_) {
        int n = idx >> 7, t = idx & 127;
        h[idx] = emb[z[n] * H_ + t];
    }
}

// ---------------- edge geometry: d, C(cosine cutoff) ----------------
__global__ void geom_kernel(const float* __restrict__ pos, const int* __restrict__ er,
                            const int* __restrict__ ec, float* __restrict__ dE,
                            float* __restrict__ CE) {
    int e = blockIdx.x * blockDim.x + threadIdx.x;
    if (e < E_) {
        int r = er[e], c = ec[e];
        float dx = pos[r*3+0] - pos[c*3+0];
        float dy = pos[r*3+1] - pos[c*3+1];
        float dz = pos[r*3+2] - pos[c*3+2];
        float d = sqrtf(dx*dx + dy*dy + dz*dz);
        dE[e] = d;
        CE[e] = 0.5f * (cosf(d * (PI_ / CUTOFF)) + 1.0f);
    }
}

// ---------------- node GEMM: C[M,128] = act(A[M,128] @ W[128,128] + b) (+ resid) ----------------
// 64x128 tile, 256 threads, 8 rows x 4 cols per thread.
__global__ void gemm128_kernel(const float* __restrict__ A, const float* __restrict__ W,
                               const float* __restrict__ bias, const float* __restrict__ resid,
                               float* __restrict__ Cout, int M, int act) {
    __shared__ float Ash[64][16];
    __shared__ float Wsh[16][128];
    int tid = threadIdx.x;
    int tc = tid & 31;       // col group: cols 4*tc..4*tc+3
    int tr = tid >> 5;       // row group: rows tr*8..tr*8+7
    int m0 = blockIdx.x * 64;

    float acc[8][4];
#pragma unroll
    for (int r = 0; r < 8; r++)
#pragma unroll
        for (int c = 0; c < 4; c++) acc[r][c] = 0.0f;

    for (int k0 = 0; k0 < 128; k0 += 16) {
        // stage A tile (64x16)
        {
            int r = tid >> 2;
            int kq = (tid & 3) * 4;
            int m = m0 + r; if (m >= M) m = M - 1;
            float4 av = *(const float4*)(A + (long)m * 128 + k0 + kq);
            *(float4*)&Ash[r][kq] = av;
        }
        // stage W tile (16x128)
        {
            int kk = tid >> 4;
            int c0 = (tid & 15) * 8;
            const float* wp = W + (long)(k0 + kk) * 128 + c0;
            float4 w0 = *(const float4*)(wp);
            float4 w1 = *(const float4*)(wp + 4);
            *(float4*)&Wsh[kk][c0]     = w0;
            *(float4*)&Wsh[kk][c0 + 4] = w1;
        }
        __syncthreads();
#pragma unroll
        for (int kk = 0; kk < 16; kk++) {
            float4 wv = *(float4*)&Wsh[kk][tc * 4];
            float a[8];
#pragma unroll
            for (int rr = 0; rr < 8; rr++) a[rr] = Ash[tr * 8 + rr][kk];
#pragma unroll
            for (int rr = 0; rr < 8; rr++) {
                acc[rr][0] += a[rr] * wv.x;
                acc[rr][1] += a[rr] * wv.y;
                acc[rr][2] += a[rr] * wv.z;
                acc[rr][3] += a[rr] * wv.w;
            }
        }
        __syncthreads();
    }

    float4 bv = make_float4(0.f, 0.f, 0.f, 0.f);
    if (bias) bv = *(const float4*)(bias + tc * 4);
#pragma unroll
    for (int rr = 0; rr < 8; rr++) {
        int m = m0 + tr * 8 + rr;
        if (m < M) {
            float4 o;
            o.x = acc[rr][0] + bv.x;
            o.y = acc[rr][1] + bv.y;
            o.z = acc[rr][2] + bv.z;
            o.w = acc[rr][3] + bv.w;
            if (act == 1) { o.x = sspf(o.x); o.y = sspf(o.y); o.z = sspf(o.z); o.w = sspf(o.w); }
            if (resid) {
                float4 rv = *(const float4*)(resid + (long)m * 128 + tc * 4);
                o.x += rv.x; o.y += rv.y; o.z += rv.z; o.w += rv.w;
            }
            *(float4*)(Cout + (long)m * 128 + tc * 4) = o;
        }
    }
}

// ---------------- fused edge kernel ----------------
// per warp: 4 edges at a time, 4 channels per thread.
// smem: w1[50*128], w2[128*128], b1[128], b2[128], per-warp ea[4][52] + t1[4][128]
constexpr int EW_THREADS = 512;
constexpr int EW_WARPS   = EW_THREADS / 32;
constexpr int WARP_SM    = 4 * 52 + 4 * 128;  // 720 floats
constexpr int EDGE_SMEM_FLOATS = G_ * NF_ + NF_ * NF_ + NF_ + NF_ + EW_WARPS * WARP_SM;
constexpr int EDGE_SMEM_BYTES  = EDGE_SMEM_FLOATS * 4;

__global__ void edge_kernel(const float* __restrict__ dE, const float* __restrict__ CE,
                            const int* __restrict__ erow, const int* __restrict__ ecol,
                            const float* __restrict__ xf, float* __restrict__ agg,
                            const float* __restrict__ w1, const float* __restrict__ b1,
                            const float* __restrict__ w2, const float* __restrict__ b2) {
    extern __shared__ float sm[];
    float* w1s = sm;                       // 6400
    float* w2s = w1s + G_ * NF_;           // 16384
    float* b1s = w2s + NF_ * NF_;          // 128
    float* b2s = b1s + NF_;                // 128
    float* wsm = b2s + NF_;

    int tid  = threadIdx.x;
    int lane = tid & 31;
    int w    = tid >> 5;
    float* eas = wsm + w * WARP_SM;        // [4][52]
    float* t1s = eas + 4 * 52;             // [4][128]

    for (int i = tid; i < G_ * NF_;  i += EW_THREADS) w1s[i] = w1[i];
    for (int i = tid; i < NF_ * NF_; i += EW_THREADS) w2s[i] = w2[i];
    if (tid < NF_) { b1s[tid] = b1[tid]; b2s[tid] = b2[tid]; }
    __syncthreads();

    float4 b1v = *(float4*)&b1s[lane * 4];
    float4 b2v = *(float4*)&b2s[lane * 4];

    long stride = (long)gridDim.x * EW_WARPS * 4;
    for (long e0 = ((long)blockIdx.x * EW_WARPS + w) * 4; e0 < E_; e0 += stride) {
        // ---- Gaussian smearing into warp-private smem ----
#pragma unroll
        for (int eb = 0; eb < 4; eb++) {
            long e = e0 + eb; if (e >= E_) e = E_ - 1;
            float de = dE[e];
            for (int g = lane; g < G_; g += 32) {
                float t = de - (float)g * GSTEP;
                eas[eb * 52 + g] = __expf(COEFF * t * t);
            }
        }
        __syncwarp();

        // ---- t1 = ssp(ea @ w1 + b1) ----
        float acc[4][4];
#pragma unroll
        for (int eb = 0; eb < 4; eb++) {
            acc[eb][0] = b1v.x; acc[eb][1] = b1v.y; acc[eb][2] = b1v.z; acc[eb][3] = b1v.w;
        }
#pragma unroll 10
        for (int g = 0; g < G_; g++) {
            float4 wv = *(float4*)&w1s[g * 128 + lane * 4];
#pragma unroll
            for (int eb = 0; eb < 4; eb++) {
                float a = eas[eb * 52 + g];
                acc[eb][0] += a * wv.x;
                acc[eb][1] += a * wv.y;
                acc[eb][2] += a * wv.z;
                acc[eb][3] += a * wv.w;
            }
        }
#pragma unroll
        for (int eb = 0; eb < 4; eb++) {
            float4 t;
            t.x = sspf(acc[eb][0]); t.y = sspf(acc[eb][1]);
            t.z = sspf(acc[eb][2]); t.w = sspf(acc[eb][3]);
            *(float4*)&t1s[eb * 128 + lane * 4] = t;
        }
        __syncwarp();

        // ---- W = (t1 @ w2 + b2) * C ----
        float acc2[4][4];
#pragma unroll
        for (int eb = 0; eb < 4; eb++) {
            acc2[eb][0] = b2v.x; acc2[eb][1] = b2v.y; acc2[eb][2] = b2v.z; acc2[eb][3] = b2v.w;
        }
#pragma unroll 8
        for (int f = 0; f < NF_; f++) {
            float4 wv = *(float4*)&w2s[f * 128 + lane * 4];
#pragma unroll
            for (int eb = 0; eb < 4; eb++) {
                float a = t1s[eb * 128 + f];
                acc2[eb][0] += a * wv.x;
                acc2[eb][1] += a * wv.y;
                acc2[eb][2] += a * wv.z;
                acc2[eb][3] += a * wv.w;
            }
        }

        // ---- msg = xf[row] * W * C ; atomic scatter into agg[col] ----
#pragma unroll
        for (int eb = 0; eb < 4; eb++) {
            long e = e0 + eb;
            if (e < E_) {
                float Ce = CE[e];
                int r = erow[e];
                int c = ecol[e];
                float4 xv = *(const float4*)(xf + (long)r * 128 + lane * 4);
                float m0v = xv.x * acc2[eb][0] * Ce;
                float m1v = xv.y * acc2[eb][1] * Ce;
                float m2v = xv.z * acc2[eb][2] * Ce;
                float m3v = xv.w * acc2[eb][3] * Ce;
                float* ap = agg + (long)c * 128 + lane * 4;
                atomicAdd(ap + 0, m0v);
                atomicAdd(ap + 1, m1v);
                atomicAdd(ap + 2, m2v);
                atomicAdd(ap + 3, m3v);
            }
        }
        __syncwarp();
    }
}

// ---------------- segment-sum scatters ----------------
__global__ void scatter_conf(const float* __restrict__ h2, const int* __restrict__ a2c,
                             float* __restrict__ conf) {
    int idx = blockIdx.x * blockDim.x + threadIdx.x;
    if (idx < N_ * H_) {
        int n = idx >> 7, t = idx & 127;
        atomicAdd(&conf[a2c[n] * H_ + t], h2[idx]);
    }
}
__global__ void scatter_mol(const float* __restrict__ conf, const int* __restrict__ c2m,
                            float* __restrict__ mol) {
    int idx = blockIdx.x * blockDim.x + threadIdx.x;
    if (idx < NC_ * H_) {
        int c = idx >> 7, t = idx & 127;
        atomicAdd(&mol[c2m[c] * H_ + t], conf[idx]);
    }
}

// ---------------- head: out[m] = ssp(mol @ hw1 + hb1) @ hw2 + hb2 ----------------
__global__ void head_kernel(const float* __restrict__ mol,
                            const float* __restrict__ w1, const float* __restrict__ b1,
                            const float* __restrict__ w2, const float* __restrict__ b2,
                            float* __restrict__ out) {
    int m = blockIdx.x;
    int j = threadIdx.x;  // 64 threads
    const float* mv = mol + (long)m * H_;
    float acc = b1[j];
    for (int k = 0; k < H_; k++) acc += mv[k] * w1[k * 64 + j];
    float s = sspf(acc) * w2[j];
    __shared__ float red[2];
#pragma unroll
    for (int o = 16; o; o >>= 1) s += __shfl_down_sync(0xffffffff, s, o);
    if ((j & 31) == 0) red[j >> 5] = s;
    __syncthreads();
    if (j == 0) out[m] = red[0] + red[1] + b2[0];
}

// ---------------- driver ----------------
extern "C" void kernel_launch(void* const* d_in, const int* in_sizes, int n_in,
                              void* d_out, int out_size) {
    const int*   z     = (const int*)  d_in[0];
    const float* pos   = (const float*)d_in[1];
    const int*   erow  = (const int*)  d_in[2];
    const int*   ecol  = (const int*)  d_in[3];
    const int*   a2c   = (const int*)  d_in[4];
    const int*   c2m   = (const int*)  d_in[5];
    const float* emb   = (const float*)d_in[6];
    const float* mw1   = (const float*)d_in[7];
    const float* mb1   = (const float*)d_in[8];
    const float* mw2   = (const float*)d_in[9];
    const float* mb2   = (const float*)d_in[10];
    const float* c1w   = (const float*)d_in[11];
    const float* c2w   = (const float*)d_in[12];
    const float* c2b   = (const float*)d_in[13];
    const float* iw    = (const float*)d_in[14];
    const float* ib    = (const float*)d_in[15];
    const float* l1w   = (const float*)d_in[16];
    const float* l1b   = (const float*)d_in[17];
    const float* l2w   = (const float*)d_in[18];
    const float* l2b   = (const float*)d_in[19];
    const float* hw1   = (const float*)d_in[20];
    const float* hb1   = (const float*)d_in[21];
    const float* hw2   = (const float*)d_in[22];
    const float* hb2   = (const float*)d_in[23];
    float* out = (float*)d_out;

    float *h, *xf, *agg, *tmp, *h2, *dE, *CEp, *conf, *mol;
    cudaGetSymbolAddress((void**)&h,    g_h);
    cudaGetSymbolAddress((void**)&xf,   g_xf);
    cudaGetSymbolAddress((void**)&agg,  g_agg);
    cudaGetSymbolAddress((void**)&tmp,  g_tmp);
    cudaGetSymbolAddress((void**)&h2,   g_h2);
    cudaGetSymbolAddress((void**)&dE,   g_dE);
    cudaGetSymbolAddress((void**)&CEp,  g_CE);
    cudaGetSymbolAddress((void**)&conf, g_conf);
    cudaGetSymbolAddress((void**)&mol,  g_mol);

    cudaFuncSetAttribute(edge_kernel, cudaFuncAttributeMaxDynamicSharedMemorySize,
                         EDGE_SMEM_BYTES);

    const int GB = (N_ + 63) / 64;

    embed_kernel<<<(N_ * H_ + 255) / 256, 256>>>(z, emb, h);
    geom_kernel<<<(E_ + 255) / 256, 256>>>(pos, erow, ecol, dE, CEp);

    for (int i = 0; i < L_; i++) {
        gemm128_kernel<<<GB, 256>>>(h, c1w + (long)i * H_ * NF_, nullptr, nullptr, xf, N_, 0);
        cudaMemsetAsync(agg, 0, (size_t)N_ * NF_ * sizeof(float));
        edge_kernel<<<148, EW_THREADS, EDGE_SMEM_BYTES>>>(
            dE, CEp, erow, ecol, xf, agg,
            mw1 + (long)i * G_ * NF_, mb1 + (long)i * NF_,
            mw2 + (long)i * NF_ * NF_, mb2 + (long)i * NF_);
        gemm128_kernel<<<GB, 256>>>(agg, c2w + (long)i * NF_ * H_, c2b + (long)i * H_,
                                    nullptr, tmp, N_, 1);
        gemm128_kernel<<<GB, 256>>>(tmp, iw + (long)i * H_ * H_, ib + (long)i * H_,
                                    h, h, N_, 0);
    }

    gemm128_kernel<<<GB, 256>>>(h, l1w, l1b, nullptr, tmp, N_, 1);
    gemm128_kernel<<<GB, 256>>>(tmp, l2w, l2b, nullptr, h2, N_, 0);

    cudaMemsetAsync(conf, 0, (size_t)NC_ * H_ * sizeof(float));
    cudaMemsetAsync(mol,  0, (size_t)NM_ * H_ * sizeof(float));
    scatter_conf<<<(N_ * H_ + 255) / 256, 256>>>(h2, a2c, conf);
    scatter_mol<<<(NC_ * H_ + 255) / 256, 256>>>(conf, c2m, mol);
    head_kernel<<<NM_, 64>>>(mol, hw1, hb1, hw2, hb2, out);
}

// round 3
// speedup vs baseline: 2.7759x; 2.7759x over previous
#include <cuda_runtime.h>
#include <math.h>

// ---------------- problem constants ----------------
constexpr int N_  = 50000;
constexpr int E_  = 600000;
constexpr int H_  = 128;
constexpr int G_  = 50;
constexpr int NF_ = 128;
constexpr int L_  = 6;
constexpr int NC_ = 500;
constexpr int NM_ = 100;

constexpr float CUTOFF = 10.0f;
constexpr float GSTEP  = CUTOFF / (G_ - 1);
constexpr float COEFF  = -0.5f / (GSTEP * GSTEP);
constexpr float LOG2F_ = 0.6931471805599453f;
constexpr float PI_    = 3.14159265358979323846f;

// filter table: W(d) per layer, NB bins over [0, DMAX]
constexpr int   NB_   = 4096;
constexpr float DMAX_ = 16.0f;
constexpr float STEP_ = DMAX_ / NB_;
constexpr float INVSTEP_ = NB_ / DMAX_;

// ---------------- scratch (device globals; no allocation allowed) ----------------
__device__ float g_h   [N_ * H_];
__device__ float g_xf  [N_ * NF_];
__device__ float g_agg [N_ * NF_];
__device__ float g_tmp [N_ * H_];
__device__ float g_h2  [N_ * H_];
__device__ int   g_bin [E_];
__device__ float g_ew0 [E_];
__device__ float g_ew1 [E_];
__device__ float g_conf[NC_ * H_];
__device__ float g_mol [NM_ * H_];
__device__ float g_tab [(long)L_ * NB_ * 128];   // 12.6 MB

// ---------------- helpers ----------------
__device__ __forceinline__ float sspf(float x) {
    float ex = __expf(-fabsf(x));
    return fmaxf(x, 0.0f) + __logf(1.0f + ex) - LOG2F_;
}

__device__ __forceinline__ unsigned long long ffma2(unsigned long long a,
                                                    unsigned long long b,
                                                    unsigned long long c) {
    unsigned long long d;
    asm("fma.rn.f32x2 %0, %1, %2, %3;" : "=l"(d) : "l"(a), "l"(b), "l"(c));
    return d;
}

__device__ __forceinline__ void red_add_v4(float* p, float a, float b, float c, float d) {
    asm volatile("red.global.add.v4.f32 [%0], {%1, %2, %3, %4};"
                 :: "l"(p), "f"(a), "f"(b), "f"(c), "f"(d) : "memory");
}

// ---------------- embed: h = emb_table[z] ----------------
__global__ void embed_kernel(const int* __restrict__ z, const float* __restrict__ emb,
                             float* __restrict__ h) {
    int idx = blockIdx.x * blockDim.x + threadIdx.x;
    if (idx < N_ * H_) {
        int n = idx >> 7, t = idx & 127;
        h[idx] = emb[z[n] * H_ + t];
    }
}

// ---------------- geometry: per-edge bin + blended lerp/cutoff weights ----------------
__global__ void geom_kernel(const float* __restrict__ pos, const int* __restrict__ er,
                            const int* __restrict__ ec, int* __restrict__ bin,
                            float* __restrict__ ew0, float* __restrict__ ew1) {
    int e = blockIdx.x * blockDim.x + threadIdx.x;
    if (e < E_) {
        int r = er[e], c = ec[e];
        float dx = pos[r*3+0] - pos[c*3+0];
        float dy = pos[r*3+1] - pos[c*3+1];
        float dz = pos[r*3+2] - pos[c*3+2];
        float d = sqrtf(dx*dx + dy*dy + dz*dz);
        float C = 0.5f * (cosf(d * (PI_ / CUTOFF)) + 1.0f);
        float fb = d * INVSTEP_;
        int ib = (int)fb;
        float fr;
        if (ib >= NB_ - 1) { ib = NB_ - 2; fr = 1.0f; }   // W(d) exactly constant there
        else fr = fb - (float)ib;
        bin[e] = ib;
        ew0[e] = (1.0f - fr) * C;
        ew1[e] = fr * C;
    }
}

// ---------------- filter table build: tab[l][b][j] = (ssp(gauss(d_b)@w1+b1)@w2+b2)[j] ----------------
constexpr int TAB_CHUNKS = 128;               // bins per block = NB_/TAB_CHUNKS = 32
constexpr int TAB_SMEM = (G_*NF_ + NF_*NF_ + NF_ + 64) * 4;

__global__ void tabbuild_kernel(const float* __restrict__ mw1, const float* __restrict__ mb1,
                                const float* __restrict__ mw2, const float* __restrict__ mb2,
                                float* __restrict__ tab) {
    extern __shared__ float sm[];
    float* w1s = sm;                 // 6400
    float* w2s = w1s + G_ * NF_;     // 16384
    float* t1  = w2s + NF_ * NF_;    // 128
    float* eas = t1 + NF_;           // 64

    int layer = blockIdx.y;
    int j = threadIdx.x;             // 128 threads, one output feature each

    const float* w1 = mw1 + (long)layer * G_ * NF_;
    const float* w2 = mw2 + (long)layer * NF_ * NF_;
    for (int i = j; i < G_ * NF_;  i += 128) w1s[i] = w1[i];
    for (int i = j; i < NF_ * NF_; i += 128) w2s[i] = w2[i];
    float b1j = mb1[(long)layer * NF_ + j];
    float b2j = mb2[(long)layer * NF_ + j];
    __syncthreads();

    int b0 = blockIdx.x * (NB_ / TAB_CHUNKS);
    for (int b = b0; b < b0 + NB_ / TAB_CHUNKS; b++) {
        float d = (float)b * STEP_;
        if (j < G_) {
            float t = d - (float)j * GSTEP;
            eas[j] = __expf(COEFF * t * t);
        }
        __syncthreads();
        float z = b1j;
#pragma unroll 10
        for (int g = 0; g < G_; g++) z += eas[g] * w1s[g * 128 + j];
        t1[j] = sspf(z);
        __syncthreads();
        float Wv = b2j;
#pragma unroll 8
        for (int f = 0; f < NF_; f++) Wv += t1[f] * w2s[f * 128 + j];
        tab[((long)layer * NB_ + b) * 128 + j] = Wv;
        __syncthreads();
    }
}

// ---------------- message kernel: msg = xf[row] * lerp(tab) ; scatter into agg[col] ----------------
constexpr int MSG_EPB = 16;          // edges per block (512 threads, 1 edge per warp)

__global__ void msg_kernel(const int* __restrict__ ebin, const float* __restrict__ ew0,
                           const float* __restrict__ ew1, const int* __restrict__ erow,
                           const int* __restrict__ ecol, const float* __restrict__ xf,
                           const float* __restrict__ tab, float* __restrict__ agg) {
    int w = threadIdx.x >> 5, lane = threadIdx.x & 31;
    long e = (long)blockIdx.x * MSG_EPB + w;
    if (e >= E_) return;
    int ib = ebin[e];
    float w0 = ew0[e], w1 = ew1[e];
    int r = erow[e], c = ecol[e];
    int co = lane * 4;
    const float* trow = tab + (long)ib * 128 + co;
    float4 t0 = *(const float4*)(trow);
    float4 t1 = *(const float4*)(trow + 128);
    float4 x  = *(const float4*)(xf + (long)r * 128 + co);
    float m0 = x.x * (w0 * t0.x + w1 * t1.x);
    float m1 = x.y * (w0 * t0.y + w1 * t1.y);
    float m2 = x.z * (w0 * t0.z + w1 * t1.z);
    float m3 = x.w * (w0 * t0.w + w1 * t1.w);
    red_add_v4(agg + (long)c * 128 + co, m0, m1, m2, m3);
}

// ---------------- node GEMM (f32x2): C[M,128] = act(A@W + b) (+resid) ----------------
// 64x128 tile, 256 threads, 8 rows x 4 cols per thread, packed FFMA2.
__global__ void gemm128_kernel(const float* __restrict__ A, const float* __restrict__ W,
                               const float* __restrict__ bias, const float* __restrict__ resid,
                               float* __restrict__ Cout, int M, int act) {
    __shared__ float2 Ashd[64][16];    // duplicated pairs {a,a}
    __shared__ float  Wsh[16][128];
    int tid = threadIdx.x;
    int tc = tid & 31;
    int tr = tid >> 5;
    int m0 = blockIdx.x * 64;

    unsigned long long acc[8][2];
#pragma unroll
    for (int r = 0; r < 8; r++) { acc[r][0] = 0ull; acc[r][1] = 0ull; }

    for (int k0 = 0; k0 < 128; k0 += 16) {
        {
            int r = tid >> 2;
            int kq = (tid & 3) * 4;
            int m = m0 + r; if (m >= M) m = M - 1;
            float4 av = *(const float4*)(A + (long)m * 128 + k0 + kq);
            Ashd[r][kq + 0] = make_float2(av.x, av.x);
            Ashd[r][kq + 1] = make_float2(av.y, av.y);
            Ashd[r][kq + 2] = make_float2(av.z, av.z);
            Ashd[r][kq + 3] = make_float2(av.w, av.w);
        }
        {
            int kk = tid >> 4;
            int c0 = (tid & 15) * 8;
            const float* wp = W + (long)(k0 + kk) * 128 + c0;
            *(float4*)&Wsh[kk][c0]     = *(const float4*)(wp);
            *(float4*)&Wsh[kk][c0 + 4] = *(const float4*)(wp + 4);
        }
        __syncthreads();
#pragma unroll
        for (int kk = 0; kk < 16; kk++) {
            unsigned long long w01 = *(unsigned long long*)&Wsh[kk][tc * 4];
            unsigned long long w23 = *(unsigned long long*)&Wsh[kk][tc * 4 + 2];
#pragma unroll
            for (int rr = 0; rr < 8; rr++) {
                unsigned long long ap = *(unsigned long long*)&Ashd[tr * 8 + rr][kk];
                acc[rr][0] = ffma2(ap, w01, acc[rr][0]);
                acc[rr][1] = ffma2(ap, w23, acc[rr][1]);
            }
        }
        __syncthreads();
    }

    float4 bv = make_float4(0.f, 0.f, 0.f, 0.f);
    if (bias) bv = *(const float4*)(bias + tc * 4);
#pragma unroll
    for (int rr = 0; rr < 8; rr++) {
        int m = m0 + tr * 8 + rr;
        if (m < M) {
            float2 p01 = *(float2*)&acc[rr][0];
            float2 p23 = *(float2*)&acc[rr][1];
            float4 o;
            o.x = p01.x + bv.x;
            o.y = p01.y + bv.y;
            o.z = p23.x + bv.z;
            o.w = p23.y + bv.w;
            if (act == 1) { o.x = sspf(o.x); o.y = sspf(o.y); o.z = sspf(o.z); o.w = sspf(o.w); }
            if (resid) {
                float4 rv = *(const float4*)(resid + (long)m * 128 + tc * 4);
                o.x += rv.x; o.y += rv.y; o.z += rv.z; o.w += rv.w;
            }
            *(float4*)(Cout + (long)m * 128 + tc * 4) = o;
        }
    }
}

// ---------------- segment-sum scatters ----------------
__global__ void scatter_conf(const float* __restrict__ h2, const int* __restrict__ a2c,
                             float* __restrict__ conf) {
    int idx = blockIdx.x * blockDim.x + threadIdx.x;
    if (idx < N_ * H_) {
        int n = idx >> 7, t = idx & 127;
        atomicAdd(&conf[a2c[n] * H_ + t], h2[idx]);
    }
}
__global__ void scatter_mol(const float* __restrict__ conf, const int* __restrict__ c2m,
                            float* __restrict__ mol) {
    int idx = blockIdx.x * blockDim.x + threadIdx.x;
    if (idx < NC_ * H_) {
        int c = idx >> 7, t = idx & 127;
        atomicAdd(&mol[c2m[c] * H_ + t], conf[idx]);
    }
}

// ---------------- head ----------------
__global__ void head_kernel(const float* __restrict__ mol,
                            const float* __restrict__ w1, const float* __restrict__ b1,
                            const float* __restrict__ w2, const float* __restrict__ b2,
                            float* __restrict__ out) {
    int m = blockIdx.x;
    int j = threadIdx.x;  // 64 threads
    const float* mv = mol + (long)m * H_;
    float acc = b1[j];
    for (int k = 0; k < H_; k++) acc += mv[k] * w1[k * 64 + j];
    float s = sspf(acc) * w2[j];
    __shared__ float red[2];
#pragma unroll
    for (int o = 16; o; o >>= 1) s += __shfl_down_sync(0xffffffff, s, o);
    if ((j & 31) == 0) red[j >> 5] = s;
    __syncthreads();
    if (j == 0) out[m] = red[0] + red[1] + b2[0];
}

// ---------------- driver ----------------
extern "C" void kernel_launch(void* const* d_in, const int* in_sizes, int n_in,
                              void* d_out, int out_size) {
    const int*   z     = (const int*)  d_in[0];
    const float* pos   = (const float*)d_in[1];
    const int*   erow  = (const int*)  d_in[2];
    const int*   ecol  = (const int*)  d_in[3];
    const int*   a2c   = (const int*)  d_in[4];
    const int*   c2m   = (const int*)  d_in[5];
    const float* emb   = (const float*)d_in[6];
    const float* mw1   = (const float*)d_in[7];
    const float* mb1   = (const float*)d_in[8];
    const float* mw2   = (const float*)d_in[9];
    const float* mb2   = (const float*)d_in[10];
    const float* c1w   = (const float*)d_in[11];
    const float* c2w   = (const float*)d_in[12];
    const float* c2b   = (const float*)d_in[13];
    const float* iw    = (const float*)d_in[14];
    const float* ib    = (const float*)d_in[15];
    const float* l1w   = (const float*)d_in[16];
    const float* l1b   = (const float*)d_in[17];
    const float* l2w   = (const float*)d_in[18];
    const float* l2b   = (const float*)d_in[19];
    const float* hw1   = (const float*)d_in[20];
    const float* hb1   = (const float*)d_in[21];
    const float* hw2   = (const float*)d_in[22];
    const float* hb2   = (const float*)d_in[23];
    float* out = (float*)d_out;

    float *h, *xf, *agg, *tmp, *h2, *ew0, *ew1, *conf, *mol, *tab;
    int *ebin;
    cudaGetSymbolAddress((void**)&h,    g_h);
    cudaGetSymbolAddress((void**)&xf,   g_xf);
    cudaGetSymbolAddress((void**)&agg,  g_agg);
    cudaGetSymbolAddress((void**)&tmp,  g_tmp);
    cudaGetSymbolAddress((void**)&h2,   g_h2);
    cudaGetSymbolAddress((void**)&ebin, g_bin);
    cudaGetSymbolAddress((void**)&ew0,  g_ew0);
    cudaGetSymbolAddress((void**)&ew1,  g_ew1);
    cudaGetSymbolAddress((void**)&conf, g_conf);
    cudaGetSymbolAddress((void**)&mol,  g_mol);
    cudaGetSymbolAddress((void**)&tab,  g_tab);

    cudaFuncSetAttribute(tabbuild_kernel, cudaFuncAttributeMaxDynamicSharedMemorySize,
                         TAB_SMEM);

    const int GB = (N_ + 63) / 64;
    const int MSG_BLOCKS = (E_ + MSG_EPB - 1) / MSG_EPB;

    embed_kernel<<<(N_ * H_ + 255) / 256, 256>>>(z, emb, h);
    geom_kernel<<<(E_ + 255) / 256, 256>>>(pos, erow, ecol, ebin, ew0, ew1);
    {
        dim3 g(TAB_CHUNKS, L_);
        tabbuild_kernel<<<g, 128, TAB_SMEM>>>(mw1, mb1, mw2, mb2, tab);
    }

    for (int i = 0; i < L_; i++) {
        gemm128_kernel<<<GB, 256>>>(h, c1w + (long)i * H_ * NF_, nullptr, nullptr, xf, N_, 0);
        cudaMemsetAsync(agg, 0, (size_t)N_ * NF_ * sizeof(float));
        msg_kernel<<<MSG_BLOCKS, 32 * MSG_EPB>>>(ebin, ew0, ew1, erow, ecol, xf,
                                                 tab + (long)i * NB_ * 128, agg);
        gemm128_kernel<<<GB, 256>>>(agg, c2w + (long)i * NF_ * H_, c2b + (long)i * H_,
                                    nullptr, tmp, N_, 1);
        gemm128_kernel<<<GB, 256>>>(tmp, iw + (long)i * H_ * H_, ib + (long)i * H_,
                                    h, h, N_, 0);
    }

    gemm128_kernel<<<GB, 256>>>(h, l1w, l1b, nullptr, tmp, N_, 1);
    gemm128_kernel<<<GB, 256>>>(tmp, l2w, l2b, nullptr, h2, N_, 0);

    cudaMemsetAsync(conf, 0, (size_t)NC_ * H_ * sizeof(float));
    cudaMemsetAsync(mol,  0, (size_t)NM_ * H_ * sizeof(float));
    scatter_conf<<<(N_ * H_ + 255) / 256, 256>>>(h2, a2c, conf);
    scatter_mol<<<(NC_ * H_ + 255) / 256, 256>>>(conf, c2m, mol);
    head_kernel<<<NM_, 64>>>(mol, hw1, hb1, hw2, hb2, out);
}

// round 4
// speedup vs baseline: 3.1276x; 1.1267x over previous
#include <cuda_runtime.h>
#include <math.h>

// ---------------- problem constants ----------------
constexpr int N_  = 50000;
constexpr int E_  = 600000;
constexpr int H_  = 128;
constexpr int G_  = 50;
constexpr int NF_ = 128;
constexpr int L_  = 6;
constexpr int NC_ = 500;
constexpr int NM_ = 100;

constexpr float CUTOFF = 10.0f;
constexpr float GSTEP  = CUTOFF / (G_ - 1);
constexpr float COEFF  = -0.5f / (GSTEP * GSTEP);
constexpr float LOG2F_ = 0.6931471805599453f;
constexpr float PI_    = 3.14159265358979323846f;

// filter table: W(d) per layer, NB bins over [0, DMAX]
constexpr int   NB_   = 4096;
constexpr float DMAX_ = 16.0f;
constexpr float STEP_ = DMAX_ / NB_;
constexpr float INVSTEP_ = NB_ / DMAX_;

// ---------------- scratch (device globals; no allocation allowed) ----------------
__device__ float g_h   [N_ * H_];
__device__ float g_xf  [N_ * NF_];
__device__ float g_agg [N_ * NF_];
__device__ float g_tmp [N_ * H_];
__device__ float g_h2  [N_ * H_];
__device__ int   g_bin [E_];
__device__ float g_ew0 [E_];
__device__ float g_ew1 [E_];
__device__ float g_conf[NC_ * H_];
__device__ float g_mol [NM_ * H_];
__device__ float g_tab [(long)L_ * NB_ * 128];   // 12.6 MB
// edge sort scratch
__device__ int    g_cnt [N_];
__device__ int    g_off [N_];
__device__ int    g_pos [N_];
__device__ int    g_srow[E_];
__device__ int    g_scol[E_];
__device__ int    g_sbin[E_];
__device__ float2 g_sw01[E_];

// ---------------- helpers ----------------
__device__ __forceinline__ float sspf(float x) {
    float ex = __expf(-fabsf(x));
    return fmaxf(x, 0.0f) + __logf(1.0f + ex) - LOG2F_;
}

__device__ __forceinline__ unsigned long long ffma2(unsigned long long a,
                                                    unsigned long long b,
                                                    unsigned long long c) {
    unsigned long long d;
    asm("fma.rn.f32x2 %0, %1, %2, %3;" : "=l"(d) : "l"(a), "l"(b), "l"(c));
    return d;
}

__device__ __forceinline__ void red_add_v4(float* p, float a, float b, float c, float d) {
    asm volatile("red.global.add.v4.f32 [%0], {%1, %2, %3, %4};"
                 :: "l"(p), "f"(a), "f"(b), "f"(c), "f"(d) : "memory");
}

// ---------------- embed ----------------
__global__ void embed_kernel(const int* __restrict__ z, const float* __restrict__ emb,
                             float* __restrict__ h) {
    int idx = blockIdx.x * blockDim.x + threadIdx.x;
    if (idx < N_ * H_) {
        int n = idx >> 7, t = idx & 127;
        h[idx] = emb[z[n] * H_ + t];
    }
}

// ---------------- geometry ----------------
__global__ void geom_kernel(const float* __restrict__ pos, const int* __restrict__ er,
                            const int* __restrict__ ec, int* __restrict__ bin,
                            float* __restrict__ ew0, float* __restrict__ ew1) {
    int e = blockIdx.x * blockDim.x + threadIdx.x;
    if (e < E_) {
        int r = er[e], c = ec[e];
        float dx = pos[r*3+0] - pos[c*3+0];
        float dy = pos[r*3+1] - pos[c*3+1];
        float dz = pos[r*3+2] - pos[c*3+2];
        float d = sqrtf(dx*dx + dy*dy + dz*dz);
        float C = 0.5f * (cosf(d * (PI_ / CUTOFF)) + 1.0f);
        float fb = d * INVSTEP_;
        int ib = (int)fb;
        float fr;
        if (ib >= NB_ - 1) { ib = NB_ - 2; fr = 1.0f; }
        else fr = fb - (float)ib;
        bin[e] = ib;
        ew0[e] = (1.0f - fr) * C;
        ew1[e] = fr * C;
    }
}

// ---------------- counting sort by ecol ----------------
__global__ void count_kernel(const int* __restrict__ ec, int* __restrict__ cnt) {
    int e = blockIdx.x * blockDim.x + threadIdx.x;
    if (e < E_) atomicAdd(&cnt[ec[e]], 1);
}

__global__ void scan_kernel(const int* __restrict__ cnt, int* __restrict__ off) {
    __shared__ int wsum[32];
    __shared__ int s_carry;
    int tid = threadIdx.x, lane = tid & 31, wid = tid >> 5;
    if (tid == 0) s_carry = 0;
    __syncthreads();
    for (int base = 0; base < N_; base += 1024) {
        int i = base + tid;
        int v = (i < N_) ? cnt[i] : 0;
        int x = v;
#pragma unroll
        for (int o = 1; o < 32; o <<= 1) {
            int y = __shfl_up_sync(0xffffffffu, x, o);
            if (lane >= o) x += y;
        }
        if (lane == 31) wsum[wid] = x;
        __syncthreads();
        if (wid == 0) {
            int s = wsum[lane];
#pragma unroll
            for (int o = 1; o < 32; o <<= 1) {
                int y = __shfl_up_sync(0xffffffffu, s, o);
                if (lane >= o) s += y;
            }
            wsum[lane] = s;
        }
        __syncthreads();
        int carry = s_carry;
        int warp_excl = (wid == 0) ? 0 : wsum[wid - 1];
        if (i < N_) off[i] = carry + warp_excl + (x - v);
        __syncthreads();
        if (tid == 0) s_carry = carry + wsum[31];
        __syncthreads();
    }
}

__global__ void place_kernel(const int* __restrict__ er, const int* __restrict__ ec,
                             const int* __restrict__ bin, const float* __restrict__ ew0,
                             const float* __restrict__ ew1, int* __restrict__ posc,
                             int* __restrict__ srow, int* __restrict__ scol,
                             int* __restrict__ sbin, float2* __restrict__ sw01) {
    int e = blockIdx.x * blockDim.x + threadIdx.x;
    if (e < E_) {
        int c = ec[e];
        int slot = atomicAdd(&posc[c], 1);
        srow[slot] = er[e];
        scol[slot] = c;
        sbin[slot] = bin[e];
        sw01[slot] = make_float2(ew0[e], ew1[e]);
    }
}

// ---------------- filter table build ----------------
constexpr int TAB_CHUNKS = 128;
constexpr int TAB_SMEM = (G_*NF_ + NF_*NF_ + NF_ + 64) * 4;

__global__ void tabbuild_kernel(const float* __restrict__ mw1, const float* __restrict__ mb1,
                                const float* __restrict__ mw2, const float* __restrict__ mb2,
                                float* __restrict__ tab) {
    extern __shared__ float sm[];
    float* w1s = sm;
    float* w2s = w1s + G_ * NF_;
    float* t1  = w2s + NF_ * NF_;
    float* eas = t1 + NF_;

    int layer = blockIdx.y;
    int j = threadIdx.x;

    const float* w1 = mw1 + (long)layer * G_ * NF_;
    const float* w2 = mw2 + (long)layer * NF_ * NF_;
    for (int i = j; i < G_ * NF_;  i += 128) w1s[i] = w1[i];
    for (int i = j; i < NF_ * NF_; i += 128) w2s[i] = w2[i];
    float b1j = mb1[(long)layer * NF_ + j];
    float b2j = mb2[(long)layer * NF_ + j];
    __syncthreads();

    int b0 = blockIdx.x * (NB_ / TAB_CHUNKS);
    for (int b = b0; b < b0 + NB_ / TAB_CHUNKS; b++) {
        float d = (float)b * STEP_;
        if (j < G_) {
            float t = d - (float)j * GSTEP;
            eas[j] = __expf(COEFF * t * t);
        }
        __syncthreads();
        float z = b1j;
#pragma unroll 10
        for (int g = 0; g < G_; g++) z += eas[g] * w1s[g * 128 + j];
        t1[j] = sspf(z);
        __syncthreads();
        float Wv = b2j;
#pragma unroll 8
        for (int f = 0; f < NF_; f++) Wv += t1[f] * w2s[f * 128 + j];
        tab[((long)layer * NB_ + b) * 128 + j] = Wv;
        __syncthreads();
    }
}

// ---------------- sorted message kernel ----------------
// warp handles CH consecutive sorted edges; accumulates equal-col runs in regs.
constexpr int MSG_CH = 16;

__global__ void msg_kernel(const int* __restrict__ srow, const int* __restrict__ scol,
                           const int* __restrict__ sbin, const float2* __restrict__ sw01,
                           const float* __restrict__ xf, const float* __restrict__ tab,
                           float* __restrict__ agg) {
    int w = threadIdx.x >> 5, lane = threadIdx.x & 31;
    long base = ((long)blockIdx.x * (blockDim.x >> 5) + w) * MSG_CH;
    if (base >= E_) return;
    int co = lane * 4;
    float4 acc = make_float4(0.f, 0.f, 0.f, 0.f);
    int cur = -1;
#pragma unroll 4
    for (int i = 0; i < MSG_CH; i++) {
        long s = base + i;
        if (s >= E_) break;
        int c = scol[s];
        int r = srow[s];
        int b = sbin[s];
        float2 wv = sw01[s];
        const float* trow = tab + (long)b * 128 + co;
        float4 t0 = *(const float4*)(trow);
        float4 t1 = *(const float4*)(trow + 128);
        float4 x  = *(const float4*)(xf + (long)r * 128 + co);
        float4 m;
        m.x = x.x * (wv.x * t0.x + wv.y * t1.x);
        m.y = x.y * (wv.x * t0.y + wv.y * t1.y);
        m.z = x.z * (wv.x * t0.z + wv.y * t1.z);
        m.w = x.w * (wv.x * t0.w + wv.y * t1.w);
        if (c != cur) {
            if (cur >= 0) red_add_v4(agg + (long)cur * 128 + co, acc.x, acc.y, acc.z, acc.w);
            cur = c;
            acc = m;
        } else {
            acc.x += m.x; acc.y += m.y; acc.z += m.z; acc.w += m.w;
        }
    }
    if (cur >= 0) red_add_v4(agg + (long)cur * 128 + co, acc.x, acc.y, acc.z, acc.w);
}

// ---------------- node GEMM v2: 128x128 tile, 8x8/thread, 2D warp layout, FFMA2 ----------------
__global__ void __launch_bounds__(256, 2)
gemm128_kernel(const float* __restrict__ A, const float* __restrict__ W,
               const float* __restrict__ bias, const float* __restrict__ resid,
               float* __restrict__ Cout, int M, int act) {
    __shared__ float2 Ash[128][17];   // duplicated pairs {a,a}, padded stride
    __shared__ float  Wsh[16][128];

    int tid  = threadIdx.x;
    int lane = tid & 31;
    int w    = tid >> 5;              // 8 warps
    int wr = w >> 1;                  // 0..3 : row block of 32
    int wc = w & 1;                   // 0..1 : col block of 64
    int lr = lane >> 3;               // 0..3 : row within (interleaved)
    int lc = lane & 7;                // 0..7 : col group of 8
    int rowb = wr * 32 + lr;          // thread rows: rowb + rr*4
    int colb = wc * 64 + lc * 8;      // thread cols: colb .. colb+7
    int m0 = blockIdx.x * 128;

    unsigned long long acc[8][4];
#pragma unroll
    for (int r = 0; r < 8; r++)
#pragma unroll
        for (int c = 0; c < 4; c++) acc[r][c] = 0ull;

    for (int k0 = 0; k0 < 128; k0 += 16) {
        // stage A tile (128x16 dup-pairs)
#pragma unroll
        for (int i = 0; i < 2; i++) {
            int idx = tid * 2 + i;            // 0..511
            int r = idx >> 2;
            int kq = (idx & 3) * 4;
            int m = m0 + r; if (m >= M) m = M - 1;
            float4 av = *(const float4*)(A + (long)m * 128 + k0 + kq);
            Ash[r][kq + 0] = make_float2(av.x, av.x);
            Ash[r][kq + 1] = make_float2(av.y, av.y);
            Ash[r][kq + 2] = make_float2(av.z, av.z);
            Ash[r][kq + 3] = make_float2(av.w, av.w);
        }
        // stage W tile (16x128)
        {
            int kk = tid >> 4;
            int c0 = (tid & 15) * 8;
            const float* wp = W + (long)(k0 + kk) * 128 + c0;
            *(float4*)&Wsh[kk][c0]     = *(const float4*)(wp);
            *(float4*)&Wsh[kk][c0 + 4] = *(const float4*)(wp + 4);
        }
        __syncthreads();

        for (int kk = 0; kk < 16; kk++) {
            unsigned long long wf[4];
            wf[0] = *(unsigned long long*)&Wsh[kk][colb + 0];
            wf[1] = *(unsigned long long*)&Wsh[kk][colb + 2];
            wf[2] = *(unsigned long long*)&Wsh[kk][colb + 4];
            wf[3] = *(unsigned long long*)&Wsh[kk][colb + 6];
#pragma unroll
            for (int rr = 0; rr < 8; rr++) {
                unsigned long long ap = *(unsigned long long*)&Ash[rowb + rr * 4][kk];
                acc[rr][0] = ffma2(ap, wf[0], acc[rr][0]);
                acc[rr][1] = ffma2(ap, wf[1], acc[rr][1]);
                acc[rr][2] = ffma2(ap, wf[2], acc[rr][2]);
                acc[rr][3] = ffma2(ap, wf[3], acc[rr][3]);
            }
        }
        __syncthreads();
    }

    float4 bv0 = make_float4(0.f,0.f,0.f,0.f), bv1 = bv0;
    if (bias) {
        bv0 = *(const float4*)(bias + colb);
        bv1 = *(const float4*)(bias + colb + 4);
    }
#pragma unroll
    for (int rr = 0; rr < 8; rr++) {
        int m = m0 + rowb + rr * 4;
        if (m < M) {
            float2 p0 = *(float2*)&acc[rr][0];
            float2 p1 = *(float2*)&acc[rr][1];
            float2 p2 = *(float2*)&acc[rr][2];
            float2 p3 = *(float2*)&acc[rr][3];
            float4 o0, o1;
            o0.x = p0.x + bv0.x; o0.y = p0.y + bv0.y;
            o0.z = p1.x + bv0.z; o0.w = p1.y + bv0.w;
            o1.x = p2.x + bv1.x; o1.y = p2.y + bv1.y;
            o1.z = p3.x + bv1.z; o1.w = p3.y + bv1.w;
            if (act == 1) {
                o0.x = sspf(o0.x); o0.y = sspf(o0.y); o0.z = sspf(o0.z); o0.w = sspf(o0.w);
                o1.x = sspf(o1.x); o1.y = sspf(o1.y); o1.z = sspf(o1.z); o1.w = sspf(o1.w);
            }
            if (resid) {
                float4 rv0 = *(const float4*)(resid + (long)m * 128 + colb);
                float4 rv1 = *(const float4*)(resid + (long)m * 128 + colb + 4);
                o0.x += rv0.x; o0.y += rv0.y; o0.z += rv0.z; o0.w += rv0.w;
                o1.x += rv1.x; o1.y += rv1.y; o1.z += rv1.z; o1.w += rv1.w;
            }
            *(float4*)(Cout + (long)m * 128 + colb)     = o0;
            *(float4*)(Cout + (long)m * 128 + colb + 4) = o1;
        }
    }
}

// ---------------- segment-sum scatters ----------------
__global__ void scatter_conf(const float* __restrict__ h2, const int* __restrict__ a2c,
                             float* __restrict__ conf) {
    int idx = blockIdx.x * blockDim.x + threadIdx.x;
    if (idx < N_ * H_) {
        int n = idx >> 7, t = idx & 127;
        atomicAdd(&conf[a2c[n] * H_ + t], h2[idx]);
    }
}
__global__ void scatter_mol(const float* __restrict__ conf, const int* __restrict__ c2m,
                            float* __restrict__ mol) {
    int idx = blockIdx.x * blockDim.x + threadIdx.x;
    if (idx < NC_ * H_) {
        int c = idx >> 7, t = idx & 127;
        atomicAdd(&mol[c2m[c] * H_ + t], conf[idx]);
    }
}

// ---------------- head ----------------
__global__ void head_kernel(const float* __restrict__ mol,
                            const float* __restrict__ w1, const float* __restrict__ b1,
                            const float* __restrict__ w2, const float* __restrict__ b2,
                            float* __restrict__ out) {
    int m = blockIdx.x;
    int j = threadIdx.x;  // 64 threads
    const float* mv = mol + (long)m * H_;
    float acc = b1[j];
    for (int k = 0; k < H_; k++) acc += mv[k] * w1[k * 64 + j];
    float s = sspf(acc) * w2[j];
    __shared__ float red[2];
#pragma unroll
    for (int o = 16; o; o >>= 1) s += __shfl_down_sync(0xffffffff, s, o);
    if ((j & 31) == 0) red[j >> 5] = s;
    __syncthreads();
    if (j == 0) out[m] = red[0] + red[1] + b2[0];
}

// ---------------- driver ----------------
extern "C" void kernel_launch(void* const* d_in, const int* in_sizes, int n_in,
                              void* d_out, int out_size) {
    const int*   z     = (const int*)  d_in[0];
    const float* pos   = (const float*)d_in[1];
    const int*   erow  = (const int*)  d_in[2];
    const int*   ecol  = (const int*)  d_in[3];
    const int*   a2c   = (const int*)  d_in[4];
    const int*   c2m   = (const int*)  d_in[5];
    const float* emb   = (const float*)d_in[6];
    const float* mw1   = (const float*)d_in[7];
    const float* mb1   = (const float*)d_in[8];
    const float* mw2   = (const float*)d_in[9];
    const float* mb2   = (const float*)d_in[10];
    const float* c1w   = (const float*)d_in[11];
    const float* c2w   = (const float*)d_in[12];
    const float* c2b   = (const float*)d_in[13];
    const float* iw    = (const float*)d_in[14];
    const float* ib    = (const float*)d_in[15];
    const float* l1w   = (const float*)d_in[16];
    const float* l1b   = (const float*)d_in[17];
    const float* l2w   = (const float*)d_in[18];
    const float* l2b   = (const float*)d_in[19];
    const float* hw1   = (const float*)d_in[20];
    const float* hb1   = (const float*)d_in[21];
    const float* hw2   = (const float*)d_in[22];
    const float* hb2   = (const float*)d_in[23];
    float* out = (float*)d_out;

    float *h, *xf, *agg, *tmp, *h2, *ew0, *ew1, *conf, *mol, *tab;
    int *ebin, *cnt, *off, *posc, *srow, *scol, *sbin;
    float2* sw01;
    cudaGetSymbolAddress((void**)&h,    g_h);
    cudaGetSymbolAddress((void**)&xf,   g_xf);
    cudaGetSymbolAddress((void**)&agg,  g_agg);
    cudaGetSymbolAddress((void**)&tmp,  g_tmp);
    cudaGetSymbolAddress((void**)&h2,   g_h2);
    cudaGetSymbolAddress((void**)&ebin, g_bin);
    cudaGetSymbolAddress((void**)&ew0,  g_ew0);
    cudaGetSymbolAddress((void**)&ew1,  g_ew1);
    cudaGetSymbolAddress((void**)&conf, g_conf);
    cudaGetSymbolAddress((void**)&mol,  g_mol);
    cudaGetSymbolAddress((void**)&tab,  g_tab);
    cudaGetSymbolAddress((void**)&cnt,  g_cnt);
    cudaGetSymbolAddress((void**)&off,  g_off);
    cudaGetSymbolAddress((void**)&posc, g_pos);
    cudaGetSymbolAddress((void**)&srow, g_srow);
    cudaGetSymbolAddress((void**)&scol, g_scol);
    cudaGetSymbolAddress((void**)&sbin, g_sbin);
    cudaGetSymbolAddress((void**)&sw01, g_sw01);

    cudaFuncSetAttribute(tabbuild_kernel, cudaFuncAttributeMaxDynamicSharedMemorySize,
                         TAB_SMEM);

    const int GB = (N_ + 127) / 128;
    const int MSG_BLOCKS = (E_ + 8 * MSG_CH - 1) / (8 * MSG_CH);

    embed_kernel<<<(N_ * H_ + 255) / 256, 256>>>(z, emb, h);
    geom_kernel<<<(E_ + 255) / 256, 256>>>(pos, erow, ecol, ebin, ew0, ew1);

    // counting sort of edges by destination column
    cudaMemsetAsync(cnt, 0, N_ * sizeof(int));
    count_kernel<<<(E_ + 255) / 256, 256>>>(ecol, cnt);
    scan_kernel<<<1, 1024>>>(cnt, off);
    cudaMemcpyAsync(posc, off, N_ * sizeof(int), cudaMemcpyDeviceToDevice);
    place_kernel<<<(E_ + 255) / 256, 256>>>(erow, ecol, ebin, ew0, ew1, posc,
                                            srow, scol, sbin, sw01);

    {
        dim3 g(TAB_CHUNKS, L_);
        tabbuild_kernel<<<g, 128, TAB_SMEM>>>(mw1, mb1, mw2, mb2, tab);
    }

    for (int i = 0; i < L_; i++) {
        gemm128_kernel<<<GB, 256>>>(h, c1w + (long)i * H_ * NF_, nullptr, nullptr, xf, N_, 0);
        cudaMemsetAsync(agg, 0, (size_t)N_ * NF_ * sizeof(float));
        msg_kernel<<<MSG_BLOCKS, 256>>>(srow, scol, sbin, sw01, xf,
                                        tab + (long)i * NB_ * 128, agg);
        gemm128_kernel<<<GB, 256>>>(agg, c2w + (long)i * NF_ * H_, c2b + (long)i * H_,
                                    nullptr, tmp, N_, 1);
        gemm128_kernel<<<GB, 256>>>(tmp, iw + (long)i * H_ * H_, ib + (long)i * H_,
                                    h, h, N_, 0);
    }

    gemm128_kernel<<<GB, 256>>>(h, l1w, l1b, nullptr, tmp, N_, 1);
    gemm128_kernel<<<GB, 256>>>(tmp, l2w, l2b, nullptr, h2, N_, 0);

    cudaMemsetAsync(conf, 0, (size_t)NC_ * H_ * sizeof(float));
    cudaMemsetAsync(mol,  0, (size_t)NM_ * H_ * sizeof(float));
    scatter_conf<<<(N_ * H_ + 255) / 256, 256>>>(h2, a2c, conf);
    scatter_mol<<<(NC_ * H_ + 255) / 256, 256>>>(conf, c2m, mol);
    head_kernel<<<NM_, 64>>>(mol, hw1, hb1, hw2, hb2, out);
}

// round 9
// speedup vs baseline: 3.6706x; 1.1736x over previous
#include <cuda_runtime.h>
#include <cuda_bf16.h>
#include <math.h>
#include <stdint.h>

// ---------------- problem constants ----------------
constexpr int N_  = 50000;
constexpr int E_  = 600000;
constexpr int H_  = 128;
constexpr int G_  = 50;
constexpr int NF_ = 128;
constexpr int L_  = 6;
constexpr int NC_ = 500;
constexpr int NM_ = 100;

constexpr float CUTOFF = 10.0f;
constexpr float GSTEP  = CUTOFF / (G_ - 1);
constexpr float COEFF  = -0.5f / (GSTEP * GSTEP);
constexpr float LOG2F_ = 0.6931471805599453f;
constexpr float PI_    = 3.14159265358979323846f;

// filter table
constexpr int   NB_   = 4096;
constexpr float DMAX_ = 16.0f;
constexpr float STEP_ = DMAX_ / NB_;
constexpr float INVSTEP_ = NB_ / DMAX_;

constexpr int NWMAT = 20;            // 6 c1w + 6 c2w + 6 iw + l1w + l2w

// single dynamic-smem declaration shared by all kernels
extern __shared__ char dynsm[];

// ---------------- scratch ----------------
__device__ float g_h   [N_ * H_];
__device__ float g_xf  [N_ * NF_];
__device__ float g_agg [N_ * NF_];
__device__ float g_tmp [N_ * H_];
__device__ float g_h2  [N_ * H_];
__device__ int   g_bin [E_];
__device__ float g_ew0 [E_];
__device__ float g_ew1 [E_];
__device__ float g_conf[NC_ * H_];
__device__ float g_mol [NM_ * H_];
__device__ float g_tab [(long)L_ * NB_ * 128];
// edge sort scratch
__device__ int    g_cnt [N_];
__device__ int    g_off [N_];
__device__ int    g_pos [N_];
__device__ int    g_bsum[256];
__device__ int    g_srow[E_];
__device__ int    g_scol[E_];
__device__ int    g_sbin[E_];
__device__ float2 g_sw01[E_];
// split weight images: [mat][ hi: n*128+k (16384) | lo: 16384 ] bf16
__device__ __nv_bfloat16 g_wsplit[(long)NWMAT * 32768];

// ---------------- helpers ----------------
__device__ __forceinline__ float sspf(float x) {
    float ex = __expf(-fabsf(x));
    return fmaxf(x, 0.0f) + __logf(1.0f + ex) - LOG2F_;
}

__device__ __forceinline__ void red_add_v4(float* p, float a, float b, float c, float d) {
    asm volatile("red.global.add.v4.f32 [%0], {%1, %2, %3, %4};"
                 :: "l"(p), "f"(a), "f"(b), "f"(c), "f"(d) : "memory");
}

__device__ __forceinline__ uint32_t smem_u32(const void* p) {
    uint32_t a;
    asm("{ .reg .u64 t; cvta.to.shared.u64 t, %1; cvt.u32.u64 %0, t; }" : "=r"(a) : "l"(p));
    return a;
}

__device__ __forceinline__ void ldm_x4(uint32_t& r0, uint32_t& r1, uint32_t& r2, uint32_t& r3,
                                       uint32_t addr) {
    asm volatile("ldmatrix.sync.aligned.m8n8.x4.shared.b16 {%0,%1,%2,%3}, [%4];"
                 : "=r"(r0), "=r"(r1), "=r"(r2), "=r"(r3) : "r"(addr));
}

__device__ __forceinline__ void mma16816(float* d, const uint32_t* a, const uint32_t* b) {
    asm volatile(
        "mma.sync.aligned.m16n8k16.row.col.f32.bf16.bf16.f32 "
        "{%0,%1,%2,%3}, {%4,%5,%6,%7}, {%8,%9}, {%0,%1,%2,%3};"
        : "+f"(d[0]), "+f"(d[1]), "+f"(d[2]), "+f"(d[3])
        : "r"(a[0]), "r"(a[1]), "r"(a[2]), "r"(a[3]), "r"(b[0]), "r"(b[1]));
}

// ---------------- embed ----------------
__global__ void embed_kernel(const int* __restrict__ z, const float* __restrict__ emb,
                             float* __restrict__ h) {
    int idx = blockIdx.x * blockDim.x + threadIdx.x;
    if (idx < N_ * H_) {
        int n = idx >> 7, t = idx & 127;
        h[idx] = emb[z[n] * H_ + t];
    }
}

// ---------------- geometry ----------------
__global__ void geom_kernel(const float* __restrict__ pos, const int* __restrict__ er,
                            const int* __restrict__ ec, int* __restrict__ bin,
                            float* __restrict__ ew0, float* __restrict__ ew1) {
    int e = blockIdx.x * blockDim.x + threadIdx.x;
    if (e < E_) {
        int r = er[e], c = ec[e];
        float dx = pos[r*3+0] - pos[c*3+0];
        float dy = pos[r*3+1] - pos[c*3+1];
        float dz = pos[r*3+2] - pos[c*3+2];
        float d = sqrtf(dx*dx + dy*dy + dz*dz);
        float C = 0.5f * (cosf(d * (PI_ / CUTOFF)) + 1.0f);
        float fb = d * INVSTEP_;
        int ib = (int)fb;
        float fr;
        if (ib >= NB_ - 1) { ib = NB_ - 2; fr = 1.0f; }
        else fr = fb - (float)ib;
        bin[e] = ib;
        ew0[e] = (1.0f - fr) * C;
        ew1[e] = fr * C;
    }
}

// ---------------- counting sort by ecol (multi-block scan) ----------------
constexpr int SCB = 256;
constexpr int NB_BLOCKS = (N_ + SCB - 1) / SCB;   // 196

__global__ void count_kernel(const int* __restrict__ ec, int* __restrict__ cnt) {
    int e = blockIdx.x * blockDim.x + threadIdx.x;
    if (e < E_) atomicAdd(&cnt[ec[e]], 1);
}

__global__ void bsum_kernel(const int* __restrict__ cnt, int* __restrict__ bsum) {
    __shared__ int ws[8];
    int t = threadIdx.x, lane = t & 31, w = t >> 5;
    int i = blockIdx.x * SCB + t;
    int v = (i < N_) ? cnt[i] : 0;
#pragma unroll
    for (int o = 16; o; o >>= 1) v += __shfl_down_sync(0xffffffffu, v, o);
    if (lane == 0) ws[w] = v;
    __syncthreads();
    if (t == 0) {
        int s = 0;
#pragma unroll
        for (int k = 0; k < 8; k++) s += ws[k];
        bsum[blockIdx.x] = s;
    }
}

__global__ void bscan_kernel(int* __restrict__ bsum) {
    __shared__ int s[256];
    int t = threadIdx.x;
    int v = (t < NB_BLOCKS) ? bsum[t] : 0;
    s[t] = v;
    __syncthreads();
    for (int o = 1; o < 256; o <<= 1) {
        int x = (t >= o) ? s[t - o] : 0;
        __syncthreads();
        s[t] += x;
        __syncthreads();
    }
    if (t < NB_BLOCKS) bsum[t] = s[t] - v;   // exclusive
}

__global__ void lscan_kernel(const int* __restrict__ cnt, const int* __restrict__ bsum,
                             int* __restrict__ off) {
    __shared__ int ws[8];
    int t = threadIdx.x, lane = t & 31, w = t >> 5;
    int i = blockIdx.x * SCB + t;
    int v = (i < N_) ? cnt[i] : 0;
    int x = v;
#pragma unroll
    for (int o = 1; o < 32; o <<= 1) {
        int y = __shfl_up_sync(0xffffffffu, x, o);
        if (lane >= o) x += y;
    }
    if (lane == 31) ws[w] = x;
    __syncthreads();
    int wexcl = 0;
    if (w > 0) {
#pragma unroll
        for (int k = 0; k < 7; k++) if (k < w) wexcl += ws[k];
    }
    if (i < N_) off[i] = bsum[blockIdx.x] + wexcl + (x - v);
}

__global__ void place_kernel(const int* __restrict__ er, const int* __restrict__ ec,
                             const int* __restrict__ bin, const float* __restrict__ ew0,
                             const float* __restrict__ ew1, int* __restrict__ posc,
                             int* __restrict__ srow, int* __restrict__ scol,
                             int* __restrict__ sbin, float2* __restrict__ sw01) {
    int e = blockIdx.x * blockDim.x + threadIdx.x;
    if (e < E_) {
        int c = ec[e];
        int slot = atomicAdd(&posc[c], 1);
        srow[slot] = er[e];
        scol[slot] = c;
        sbin[slot] = bin[e];
        sw01[slot] = make_float2(ew0[e], ew1[e]);
    }
}

// ---------------- filter table build ----------------
constexpr int TAB_CHUNKS = 128;
constexpr int TAB_SMEM = (G_*NF_ + NF_*NF_ + NF_ + 64) * 4;

__global__ void tabbuild_kernel(const float* __restrict__ mw1, const float* __restrict__ mb1,
                                const float* __restrict__ mw2, const float* __restrict__ mb2,
                                float* __restrict__ tab) {
    float* sm = (float*)dynsm;
    float* w1s = sm;
    float* w2s = w1s + G_ * NF_;
    float* t1  = w2s + NF_ * NF_;
    float* eas = t1 + NF_;

    int layer = blockIdx.y;
    int j = threadIdx.x;

    const float* w1 = mw1 + (long)layer * G_ * NF_;
    const float* w2 = mw2 + (long)layer * NF_ * NF_;
    for (int i = j; i < G_ * NF_;  i += 128) w1s[i] = w1[i];
    for (int i = j; i < NF_ * NF_; i += 128) w2s[i] = w2[i];
    float b1j = mb1[(long)layer * NF_ + j];
    float b2j = mb2[(long)layer * NF_ + j];
    __syncthreads();

    int b0 = blockIdx.x * (NB_ / TAB_CHUNKS);
    for (int b = b0; b < b0 + NB_ / TAB_CHUNKS; b++) {
        float d = (float)b * STEP_;
        if (j < G_) {
            float t = d - (float)j * GSTEP;
            eas[j] = __expf(COEFF * t * t);
        }
        __syncthreads();
        float z = b1j;
#pragma unroll 10
        for (int g = 0; g < G_; g++) z += eas[g] * w1s[g * 128 + j];
        t1[j] = sspf(z);
        __syncthreads();
        float Wv = b2j;
#pragma unroll 8
        for (int f = 0; f < NF_; f++) Wv += t1[f] * w2s[f * 128 + j];
        tab[((long)layer * NB_ + b) * 128 + j] = Wv;
        __syncthreads();
    }
}

// ---------------- sorted message kernel ----------------
constexpr int MSG_CH = 16;

__global__ void msg_kernel(const int* __restrict__ srow, const int* __restrict__ scol,
                           const int* __restrict__ sbin, const float2* __restrict__ sw01,
                           const float* __restrict__ xf, const float* __restrict__ tab,
                           float* __restrict__ agg) {
    int w = threadIdx.x >> 5, lane = threadIdx.x & 31;
    long base = ((long)blockIdx.x * (blockDim.x >> 5) + w) * MSG_CH;
    if (base >= E_) return;
    int co = lane * 4;
    float4 acc = make_float4(0.f, 0.f, 0.f, 0.f);
    int cur = -1;
#pragma unroll 4
    for (int i = 0; i < MSG_CH; i++) {
        long s = base + i;
        if (s >= E_) break;
        int c = scol[s];
        int r = srow[s];
        int b = sbin[s];
        float2 wv = sw01[s];
        const float* trow = tab + (long)b * 128 + co;
        float4 t0 = *(const float4*)(trow);
        float4 t1 = *(const float4*)(trow + 128);
        float4 x  = *(const float4*)(xf + (long)r * 128 + co);
        float4 m;
        m.x = x.x * (wv.x * t0.x + wv.y * t1.x);
        m.y = x.y * (wv.x * t0.y + wv.y * t1.y);
        m.z = x.z * (wv.x * t0.z + wv.y * t1.z);
        m.w = x.w * (wv.x * t0.w + wv.y * t1.w);
        if (c != cur) {
            if (cur >= 0) red_add_v4(agg + (long)cur * 128 + co, acc.x, acc.y, acc.z, acc.w);
            cur = c;
            acc = m;
        } else {
            acc.x += m.x; acc.y += m.y; acc.z += m.z; acc.w += m.w;
        }
    }
    if (cur >= 0) red_add_v4(agg + (long)cur * 128 + co, acc.x, acc.y, acc.z, acc.w);
}

// ---------------- weight prep: split fp32 W[k][n] -> hi/lo bf16 compact [n][k] ----------------
__global__ void wprep_kernel(const float* __restrict__ c1w, const float* __restrict__ c2w,
                             const float* __restrict__ iw, const float* __restrict__ l1w,
                             const float* __restrict__ l2w, __nv_bfloat16* __restrict__ ws) {
    int mat = blockIdx.x;
    const float* W;
    if      (mat < 6)  W = c1w + (long)mat * 16384;
    else if (mat < 12) W = c2w + (long)(mat - 6) * 16384;
    else if (mat < 18) W = iw  + (long)(mat - 12) * 16384;
    else if (mat == 18) W = l1w;
    else                W = l2w;
    __nv_bfloat16* hi = ws + (long)mat * 32768;
    __nv_bfloat16* lo = hi + 16384;
    for (int idx = threadIdx.x; idx < 16384; idx += blockDim.x) {
        int n = idx >> 7, k = idx & 127;
        float w = W[k * 128 + n];
        __nv_bfloat16 h = __float2bfloat16(w);
        __nv_bfloat16 l = __float2bfloat16(w - __bfloat162float(h));
        hi[n * 128 + k] = h;
        lo[n * 128 + k] = l;
    }
}

// ---------------- HMMA GEMM: C[M,128] = act(A@W + b) (+resid), split bf16 x3 ----------------
// 128x128 tile/block, 256 threads, warp grid 4(m) x 2(n), warp tile 32x64.
// smem rows padded to 136 bf16 (272B = 17*16B) -> ldmatrix conflict-free.
constexpr int PADK = 136;
constexpr int TILE_E = 128 * PADK;                 // elements per operand image
constexpr int GH_SMEM = 4 * TILE_E * 2;            // 139264 bytes

__global__ void __launch_bounds__(256, 1)
gemm_hmma(const float* __restrict__ A, const __nv_bfloat16* __restrict__ wimg,
          const float* __restrict__ bias, const float* __restrict__ resid,
          float* __restrict__ Cout, int M, int act) {
    __nv_bfloat16* Ahs = (__nv_bfloat16*)dynsm;
    __nv_bfloat16* Als = Ahs + TILE_E;
    __nv_bfloat16* Whs = Als + TILE_E;
    __nv_bfloat16* Wls = Whs + TILE_E;
    float* Dsm = (float*)dynsm;                    // reused for epilogue
    uint32_t smb = smem_u32(dynsm);

    int tid = threadIdx.x;
    int wid = tid >> 5;
    int lane = tid & 31;
    int wm = wid & 3;         // row block of 32
    int wn = wid >> 2;        // col block of 64
    int m0 = blockIdx.x * 128;

    // ---- stage A: fp32 -> hi/lo bf16, padded rows ----
    for (int idx = tid; idx < 128 * 32; idx += 256) {
        int row = idx >> 5;
        int kq = (idx & 31) * 4;
        int m = m0 + row; if (m >= M) m = M - 1;
        float4 a = *(const float4*)(A + (long)m * 128 + kq);
        __nv_bfloat16 h0 = __float2bfloat16(a.x), h1 = __float2bfloat16(a.y);
        __nv_bfloat16 h2 = __float2bfloat16(a.z), h3 = __float2bfloat16(a.w);
        __nv_bfloat16 l0 = __float2bfloat16(a.x - __bfloat162float(h0));
        __nv_bfloat16 l1 = __float2bfloat16(a.y - __bfloat162float(h1));
        __nv_bfloat16 l2 = __float2bfloat16(a.z - __bfloat162float(h2));
        __nv_bfloat16 l3 = __float2bfloat16(a.w - __bfloat162float(h3));
        int o = row * PADK + kq;
        __nv_bfloat162 p01, p23, q01, q23;
        p01.x = h0; p01.y = h1; p23.x = h2; p23.y = h3;
        q01.x = l0; q01.y = l1; q23.x = l2; q23.y = l3;
        *(__nv_bfloat162*)(Ahs + o)     = p01;
        *(__nv_bfloat162*)(Ahs + o + 2) = p23;
        *(__nv_bfloat162*)(Als + o)     = q01;
        *(__nv_bfloat162*)(Als + o + 2) = q23;
    }
    // ---- stage W (compact [n][k] in gmem -> padded rows) ----
    for (int idx = tid; idx < 128 * 16; idx += 256) {
        int n = idx >> 4;
        int c = (idx & 15) * 8;
        *(float4*)(Whs + n * PADK + c) = *(const float4*)(wimg + n * 128 + c);
        *(float4*)(Wls + n * PADK + c) = *(const float4*)(wimg + 16384 + n * 128 + c);
    }
    __syncthreads();

    // ---- compute: 3 passes (AhWh, AhWl, AlWh) accumulated in fp32 C frags ----
    float c[2][8][4];
#pragma unroll
    for (int mi = 0; mi < 2; mi++)
#pragma unroll
        for (int ni = 0; ni < 8; ni++)
#pragma unroll
            for (int q = 0; q < 4; q++) c[mi][ni][q] = 0.0f;

    // per-thread base offsets (bytes)
    uint32_t a_row = (uint32_t)(wm * 32 + (lane & 15));
    uint32_t a_base = smb + 2 * (a_row * PADK + ((lane >> 4) << 3));
    uint32_t b_row = (uint32_t)(wn * 64 + ((lane >> 4) << 3) + (lane & 7));
    uint32_t b_base = smb + 2 * (b_row * PADK + (((lane >> 3) & 1) << 3));

    const uint32_t AOFF[3] = {0u, 0u, (uint32_t)(TILE_E * 2)};
    const uint32_t BOFF[3] = {(uint32_t)(2 * TILE_E * 2), (uint32_t)(3 * TILE_E * 2),
                              (uint32_t)(2 * TILE_E * 2)};

#pragma unroll
    for (int p = 0; p < 3; p++) {
        uint32_t ab = a_base + AOFF[p];
        uint32_t bb = b_base + BOFF[p];
#pragma unroll
        for (int kk = 0; kk < 8; kk++) {
            uint32_t koff = (uint32_t)(kk * 16 * 2);
            uint32_t afr[2][4];
            ldm_x4(afr[0][0], afr[0][1], afr[0][2], afr[0][3], ab + koff);
            ldm_x4(afr[1][0], afr[1][1], afr[1][2], afr[1][3],
                   ab + koff + 2 * 16 * PADK);
            uint32_t bfr[8][2];
#pragma unroll
            for (int j = 0; j < 4; j++) {
                uint32_t r0, r1, r2, r3;
                ldm_x4(r0, r1, r2, r3, bb + koff + 2 * (uint32_t)(j * 16 * PADK));
                bfr[2*j][0] = r0; bfr[2*j][1] = r1;
                bfr[2*j+1][0] = r2; bfr[2*j+1][1] = r3;
            }
#pragma unroll
            for (int mi = 0; mi < 2; mi++)
#pragma unroll
                for (int ni = 0; ni < 8; ni++)
                    mma16816(c[mi][ni], afr[mi], bfr[ni]);
        }
    }
    __syncthreads();   // all ldmatrix reads done before smem reuse

    // ---- C frags -> Dsm (row-major, stride 132) ----
#pragma unroll
    for (int mi = 0; mi < 2; mi++) {
        int r0 = wm * 32 + mi * 16 + (lane >> 2);
#pragma unroll
        for (int ni = 0; ni < 8; ni++) {
            int col = wn * 64 + ni * 8 + 2 * (lane & 3);
            Dsm[r0 * 132 + col]       = c[mi][ni][0];
            Dsm[r0 * 132 + col + 1]   = c[mi][ni][1];
            Dsm[(r0+8) * 132 + col]   = c[mi][ni][2];
            Dsm[(r0+8) * 132 + col+1] = c[mi][ni][3];
        }
    }
    __syncthreads();

    // ---- coalesced epilogue ----
    for (int idx = tid; idx < 128 * 32; idx += 256) {
        int r2 = idx >> 5;
        int cq = (idx & 31) * 4;
        int m = m0 + r2;
        if (m < M) {
            float4 o;
            o.x = Dsm[r2 * 132 + cq + 0];
            o.y = Dsm[r2 * 132 + cq + 1];
            o.z = Dsm[r2 * 132 + cq + 2];
            o.w = Dsm[r2 * 132 + cq + 3];
            if (bias) {
                float4 bv = *(const float4*)(bias + cq);
                o.x += bv.x; o.y += bv.y; o.z += bv.z; o.w += bv.w;
            }
            if (act == 1) { o.x = sspf(o.x); o.y = sspf(o.y); o.z = sspf(o.z); o.w = sspf(o.w); }
            if (resid) {
                float4 rv = *(const float4*)(resid + (long)m * 128 + cq);
                o.x += rv.x; o.y += rv.y; o.z += rv.z; o.w += rv.w;
            }
            *(float4*)(Cout + (long)m * 128 + cq) = o;
        }
    }
}

// ---------------- segment-sum scatters ----------------
__global__ void scatter_conf(const float* __restrict__ h2, const int* __restrict__ a2c,
                             float* __restrict__ conf) {
    int idx = blockIdx.x * blockDim.x + threadIdx.x;
    if (idx < N_ * H_) {
        int n = idx >> 7, t = idx & 127;
        atomicAdd(&conf[a2c[n] * H_ + t], h2[idx]);
    }
}
__global__ void scatter_mol(const float* __restrict__ conf, const int* __restrict__ c2m,
                            float* __restrict__ mol) {
    int idx = blockIdx.x * blockDim.x + threadIdx.x;
    if (idx < NC_ * H_) {
        int c = idx >> 7, t = idx & 127;
        atomicAdd(&mol[c2m[c] * H_ + t], conf[idx]);
    }
}

// ---------------- head ----------------
__global__ void head_kernel(const float* __restrict__ mol,
                            const float* __restrict__ w1, const float* __restrict__ b1,
                            const float* __restrict__ w2, const float* __restrict__ b2,
                            float* __restrict__ out) {
    int m = blockIdx.x;
    int j = threadIdx.x;  // 64 threads
    const float* mv = mol + (long)m * H_;
    float acc = b1[j];
    for (int k = 0; k < H_; k++) acc += mv[k] * w1[k * 64 + j];
    float s = sspf(acc) * w2[j];
    __shared__ float red[2];
#pragma unroll
    for (int o = 16; o; o >>= 1) s += __shfl_down_sync(0xffffffff, s, o);
    if ((j & 31) == 0) red[j >> 5] = s;
    __syncthreads();
    if (j == 0) out[m] = red[0] + red[1] + b2[0];
}

// ---------------- driver ----------------
extern "C" void kernel_launch(void* const* d_in, const int* in_sizes, int n_in,
                              void* d_out, int out_size) {
    const int*   z     = (const int*)  d_in[0];
    const float* pos   = (const float*)d_in[1];
    const int*   erow  = (const int*)  d_in[2];
    const int*   ecol  = (const int*)  d_in[3];
    const int*   a2c   = (const int*)  d_in[4];
    const int*   c2m   = (const int*)  d_in[5];
    const float* emb   = (const float*)d_in[6];
    const float* mw1   = (const float*)d_in[7];
    const float* mb1   = (const float*)d_in[8];
    const float* mw2   = (const float*)d_in[9];
    const float* mb2   = (const float*)d_in[10];
    const float* c1w   = (const float*)d_in[11];
    const float* c2w   = (const float*)d_in[12];
    const float* c2b   = (const float*)d_in[13];
    const float* iw    = (const float*)d_in[14];
    const float* ib    = (const float*)d_in[15];
    const float* l1w   = (const float*)d_in[16];
    const float* l1b   = (const float*)d_in[17];
    const float* l2w   = (const float*)d_in[18];
    const float* l2b   = (const float*)d_in[19];
    const float* hw1   = (const float*)d_in[20];
    const float* hb1   = (const float*)d_in[21];
    const float* hw2   = (const float*)d_in[22];
    const float* hb2   = (const float*)d_in[23];
    float* out = (float*)d_out;

    float *h, *xf, *agg, *tmp, *h2, *ew0, *ew1, *conf, *mol, *tab;
    int *ebin, *cnt, *off, *posc, *srow, *scol, *sbin, *bsum;
    float2* sw01;
    __nv_bfloat16* wsplit;
    cudaGetSymbolAddress((void**)&h,    g_h);
    cudaGetSymbolAddress((void**)&xf,   g_xf);
    cudaGetSymbolAddress((void**)&agg,  g_agg);
    cudaGetSymbolAddress((void**)&tmp,  g_tmp);
    cudaGetSymbolAddress((void**)&h2,   g_h2);
    cudaGetSymbolAddress((void**)&ebin, g_bin);
    cudaGetSymbolAddress((void**)&ew0,  g_ew0);
    cudaGetSymbolAddress((void**)&ew1,  g_ew1);
    cudaGetSymbolAddress((void**)&conf, g_conf);
    cudaGetSymbolAddress((void**)&mol,  g_mol);
    cudaGetSymbolAddress((void**)&tab,  g_tab);
    cudaGetSymbolAddress((void**)&cnt,  g_cnt);
    cudaGetSymbolAddress((void**)&off,  g_off);
    cudaGetSymbolAddress((void**)&posc, g_pos);
    cudaGetSymbolAddress((void**)&bsum, g_bsum);
    cudaGetSymbolAddress((void**)&srow, g_srow);
    cudaGetSymbolAddress((void**)&scol, g_scol);
    cudaGetSymbolAddress((void**)&sbin, g_sbin);
    cudaGetSymbolAddress((void**)&sw01, g_sw01);
    cudaGetSymbolAddress((void**)&wsplit, g_wsplit);

    cudaFuncSetAttribute(tabbuild_kernel, cudaFuncAttributeMaxDynamicSharedMemorySize, TAB_SMEM);
    cudaFuncSetAttribute(gemm_hmma, cudaFuncAttributeMaxDynamicSharedMemorySize, GH_SMEM);

    const int GTB = (N_ + 127) / 128;   // 391
    const int MSG_BLOCKS = (E_ + 8 * MSG_CH - 1) / (8 * MSG_CH);

    embed_kernel<<<(N_ * H_ + 255) / 256, 256>>>(z, emb, h);
    geom_kernel<<<(E_ + 255) / 256, 256>>>(pos, erow, ecol, ebin, ew0, ew1);
    wprep_kernel<<<NWMAT, 256>>>(c1w, c2w, iw, l1w, l2w, wsplit);

    // counting sort by destination
    cudaMemsetAsync(cnt, 0, N_ * sizeof(int));
    count_kernel<<<(E_ + 255) / 256, 256>>>(ecol, cnt);
    bsum_kernel<<<NB_BLOCKS, SCB>>>(cnt, bsum);
    bscan_kernel<<<1, 256>>>(bsum);
    lscan_kernel<<<NB_BLOCKS, SCB>>>(cnt, bsum, off);
    cudaMemcpyAsync(posc, off, N_ * sizeof(int), cudaMemcpyDeviceToDevice);
    place_kernel<<<(E_ + 255) / 256, 256>>>(erow, ecol, ebin, ew0, ew1, posc,
                                            srow, scol, sbin, sw01);

    {
        dim3 g(TAB_CHUNKS, L_);
        tabbuild_kernel<<<g, 128, TAB_SMEM>>>(mw1, mb1, mw2, mb2, tab);
    }

    for (int i = 0; i < L_; i++) {
        gemm_hmma<<<GTB, 256, GH_SMEM>>>(h, wsplit + (long)i * 32768, nullptr, nullptr, xf, N_, 0);
        cudaMemsetAsync(agg, 0, (size_t)N_ * NF_ * sizeof(float));
        msg_kernel<<<MSG_BLOCKS, 256>>>(srow, scol, sbin, sw01, xf,
                                        tab + (long)i * NB_ * 128, agg);
        gemm_hmma<<<GTB, 256, GH_SMEM>>>(agg, wsplit + (long)(6 + i) * 32768,
                                         c2b + (long)i * H_, nullptr, tmp, N_, 1);
        gemm_hmma<<<GTB, 256, GH_SMEM>>>(tmp, wsplit + (long)(12 + i) * 32768,
                                         ib + (long)i * H_, h, h, N_, 0);
    }

    gemm_hmma<<<GTB, 256, GH_SMEM>>>(h, wsplit + 18L * 32768, l1b, nullptr, tmp, N_, 1);
    gemm_hmma<<<GTB, 256, GH_SMEM>>>(tmp, wsplit + 19L * 32768, l2b, nullptr, h2, N_, 0);

    cudaMemsetAsync(conf, 0, (size_t)NC_ * H_ * sizeof(float));
    cudaMemsetAsync(mol,  0, (size_t)NM_ * H_ * sizeof(float));
    scatter_conf<<<(N_ * H_ + 255) / 256, 256>>>(h2, a2c, conf);
    scatter_mol<<<(NC_ * H_ + 255) / 256, 256>>>(conf, c2m, mol);
    head_kernel<<<NM_, 64>>>(mol, hw1, hb1, hw2, hb2, out);
}